// round 2
// baseline (speedup 1.0000x reference)
#include <cuda_runtime.h>
#include <cuda_bf16.h>
#include <math.h>

// Problem constants
#define BB 2
#define TT 2048
#define DD 1024
#define HH 16
#define HD 64
#define ROWS (BB*TT)          // 4096

// ---------------- scratch (device globals; no allocations) ----------------
__device__ float g_h   [ROWS * DD];        // LN outputs (reused)
__device__ float g_qkv [ROWS * 3 * DD];    // QKV
__device__ float g_att [ROWS * DD];        // attention output
__device__ float g_x1  [ROWS * DD];        // x + attn proj (residual stream)
__device__ float g_mid [ROWS * 4 * DD];    // MLP hidden

// ---------------- LayerNorm: one block (256 thr) per row of 1024 ----------
__global__ void ln_kernel(const float* __restrict__ x,
                          const float* __restrict__ g,
                          const float* __restrict__ bvec,
                          float* __restrict__ out) {
    int row = blockIdx.x;
    int t   = threadIdx.x;          // 256 threads, one float4 each
    const float4* xr = (const float4*)(x + (size_t)row * DD);
    float4 v = xr[t];
    float s  = v.x + v.y + v.z + v.w;
    float ss = v.x*v.x + v.y*v.y + v.z*v.z + v.w*v.w;
    #pragma unroll
    for (int o = 16; o > 0; o >>= 1) {
        s  += __shfl_xor_sync(0xffffffffu, s,  o);
        ss += __shfl_xor_sync(0xffffffffu, ss, o);
    }
    __shared__ float sh[2][8];
    int w = t >> 5, ln = t & 31;
    if (ln == 0) { sh[0][w] = s; sh[1][w] = ss; }
    __syncthreads();
    s = 0.f; ss = 0.f;
    #pragma unroll
    for (int i = 0; i < 8; i++) { s += sh[0][i]; ss += sh[1][i]; }
    float mu   = s * (1.0f / DD);
    float var  = ss * (1.0f / DD) - mu * mu;
    float rstd = rsqrtf(var + 1e-5f);
    float4 gg = ((const float4*)g)[t];
    float4 bb = ((const float4*)bvec)[t];
    float4 o4;
    o4.x = (v.x - mu) * rstd * gg.x + bb.x;
    o4.y = (v.y - mu) * rstd * gg.y + bb.y;
    o4.z = (v.z - mu) * rstd * gg.z + bb.z;
    o4.w = (v.w - mu) * rstd * gg.w + bb.w;
    ((float4*)(out + (size_t)row * DD))[t] = o4;
}

// ---------------- GEMM: C[M,N] = A[M,K] @ B[K,N] (+bias, epilogue) --------
// EPI: 0 = +bias ; 1 = +bias + residual ; 2 = +bias then exact GELU
#define BM 128
#define BN 128
#define BKK 16

__device__ __forceinline__ float gelu_exact(float v) {
    return 0.5f * v * (1.0f + erff(v * 0.70710678118654752f));
}

template <int EPI>
__global__ void __launch_bounds__(256, 2)
gemm_kernel(const float* __restrict__ A, const float* __restrict__ B,
            const float* __restrict__ bias, const float* __restrict__ res,
            float* __restrict__ C, int M, int N, int K) {
    __shared__ float As[BKK][BM];
    __shared__ float Bs[BKK][BN];

    int bx = blockIdx.x;   // N tile
    int by = blockIdx.y;   // M tile
    int tid = threadIdx.x; // 256

    int a_row  = tid >> 2;          // 0..63 (two loads: +0, +64)
    int a_col4 = (tid & 3) * 4;     // 0,4,8,12
    int b_row  = tid >> 5;          // 0..7  (two loads: +0, +8)
    int b_col4 = (tid & 31) * 4;

    int tx = tid & 15;
    int ty = tid >> 4;

    float acc[8][8];
    #pragma unroll
    for (int i = 0; i < 8; i++)
        #pragma unroll
        for (int j = 0; j < 8; j++) acc[i][j] = 0.f;

    const float* Ab = A + (size_t)by * BM * K;
    const float* Bb = B + (size_t)bx * BN;

    for (int k0 = 0; k0 < K; k0 += BKK) {
        #pragma unroll
        for (int i = 0; i < 2; i++) {
            int r = a_row + i * 64;
            float4 v = *(const float4*)&Ab[(size_t)r * K + k0 + a_col4];
            As[a_col4 + 0][r] = v.x;
            As[a_col4 + 1][r] = v.y;
            As[a_col4 + 2][r] = v.z;
            As[a_col4 + 3][r] = v.w;
        }
        #pragma unroll
        for (int i = 0; i < 2; i++) {
            int r = b_row + i * 8;
            *(float4*)&Bs[r][b_col4] =
                *(const float4*)&Bb[(size_t)(k0 + r) * N + b_col4];
        }
        __syncthreads();
        #pragma unroll
        for (int k = 0; k < BKK; k++) {
            float a[8], bf[8];
            float4 a0 = *(const float4*)&As[k][ty * 8];
            float4 a1 = *(const float4*)&As[k][ty * 8 + 4];
            float4 b0 = *(const float4*)&Bs[k][tx * 8];
            float4 b1 = *(const float4*)&Bs[k][tx * 8 + 4];
            a[0]=a0.x; a[1]=a0.y; a[2]=a0.z; a[3]=a0.w;
            a[4]=a1.x; a[5]=a1.y; a[6]=a1.z; a[7]=a1.w;
            bf[0]=b0.x; bf[1]=b0.y; bf[2]=b0.z; bf[3]=b0.w;
            bf[4]=b1.x; bf[5]=b1.y; bf[6]=b1.z; bf[7]=b1.w;
            #pragma unroll
            for (int i = 0; i < 8; i++)
                #pragma unroll
                for (int j = 0; j < 8; j++)
                    acc[i][j] += a[i] * bf[j];
        }
        __syncthreads();
    }

    // epilogue: each thread owns rows by*BM+ty*8+i, cols bx*BN+tx*8+j
    #pragma unroll
    for (int i = 0; i < 8; i++) {
        int row = by * BM + ty * 8 + i;
        int colb = bx * BN + tx * 8;
        #pragma unroll
        for (int j4 = 0; j4 < 2; j4++) {
            float4 o4;
            float* pv = &acc[i][j4 * 4];
            const float4 bia = *(const float4*)&bias[colb + j4 * 4];
            o4.x = pv[0] + bia.x;
            o4.y = pv[1] + bia.y;
            o4.z = pv[2] + bia.z;
            o4.w = pv[3] + bia.w;
            if (EPI == 1) {
                float4 r4 = *(const float4*)&res[(size_t)row * N + colb + j4 * 4];
                o4.x += r4.x; o4.y += r4.y; o4.z += r4.z; o4.w += r4.w;
            }
            if (EPI == 2) {
                o4.x = gelu_exact(o4.x);
                o4.y = gelu_exact(o4.y);
                o4.z = gelu_exact(o4.z);
                o4.w = gelu_exact(o4.w);
            }
            *(float4*)&C[(size_t)row * N + colb + j4 * 4] = o4;
        }
    }
}

// ---------------- Attention: causal flash, 1 thread = 1 query row ---------
// grid: (T/128, B*H), block 128 threads. K/V tiles of 64 rows in SMEM.
__global__ void __launch_bounds__(128)
attn_kernel() {
    int qblk = blockIdx.x;
    int bh   = blockIdx.y;
    int b = bh >> 4;
    int h = bh & 15;
    int r = threadIdx.x;           // 0..127
    int qi = qblk * 128 + r;

    const float* base = g_qkv + (size_t)b * TT * 3 * DD;

    float q[HD];
    {
        const float4* qp = (const float4*)(base + (size_t)qi * 3 * DD + h * HD);
        #pragma unroll
        for (int d4 = 0; d4 < HD / 4; d4++) {
            float4 v = qp[d4];
            q[d4*4+0] = v.x * 0.125f;
            q[d4*4+1] = v.y * 0.125f;
            q[d4*4+2] = v.z * 0.125f;
            q[d4*4+3] = v.w * 0.125f;
        }
    }

    float o[HD];
    #pragma unroll
    for (int d = 0; d < HD; d++) o[d] = 0.f;
    float m = -1e30f, l = 0.f;

    __shared__ float Ks[64][HD];
    __shared__ float Vs[64][HD];

    int kmax = qblk * 128 + 127;   // largest valid key for this block
    int lr = r >> 1;               // 0..63
    int lc = (r & 1) * 32;         // 0 or 32

    for (int kb = 0; kb * 64 <= kmax; kb++) {
        const float4* kp = (const float4*)(base + (size_t)(kb*64 + lr) * 3 * DD + DD + h * HD + lc);
        const float4* vp = (const float4*)(base + (size_t)(kb*64 + lr) * 3 * DD + 2*DD + h * HD + lc);
        #pragma unroll
        for (int i = 0; i < 8; i++) {
            ((float4*)&Ks[lr][lc])[i] = kp[i];
            ((float4*)&Vs[lr][lc])[i] = vp[i];
        }
        __syncthreads();

        int jend = qi - kb * 64 + 1;
        if (jend > 64) jend = 64;
        for (int j = 0; j < jend; j++) {
            float s = 0.f;
            const float4* kr = (const float4*)Ks[j];
            #pragma unroll
            for (int d4 = 0; d4 < HD / 4; d4++) {
                float4 kv = kr[d4];
                s += q[d4*4+0]*kv.x + q[d4*4+1]*kv.y + q[d4*4+2]*kv.z + q[d4*4+3]*kv.w;
            }
            if (s > m) {
                float sc = __expf(m - s);
                m = s;
                l *= sc;
                #pragma unroll
                for (int d = 0; d < HD; d++) o[d] *= sc;
            }
            float p = __expf(s - m);
            l += p;
            const float4* vr = (const float4*)Vs[j];
            #pragma unroll
            for (int d4 = 0; d4 < HD / 4; d4++) {
                float4 vv = vr[d4];
                o[d4*4+0] += p * vv.x;
                o[d4*4+1] += p * vv.y;
                o[d4*4+2] += p * vv.z;
                o[d4*4+3] += p * vv.w;
            }
        }
        __syncthreads();
    }

    float inv = 1.0f / l;
    float4* op = (float4*)(g_att + ((size_t)b * TT + qi) * DD + h * HD);
    #pragma unroll
    for (int d4 = 0; d4 < HD / 4; d4++) {
        float4 v;
        v.x = o[d4*4+0] * inv;
        v.y = o[d4*4+1] * inv;
        v.z = o[d4*4+2] * inv;
        v.w = o[d4*4+3] * inv;
        op[d4] = v;
    }
}

// ---------------- launch -------------------------------------------------
extern "C" void kernel_launch(void* const* d_in, const int* in_sizes, int n_in,
                              void* d_out, int out_size) {
    const float* x     = (const float*)d_in[0];
    const float* w_qkv = (const float*)d_in[1];
    const float* b_qkv = (const float*)d_in[2];
    const float* w_fc  = (const float*)d_in[3];
    const float* b_fc  = (const float*)d_in[4];
    const float* ln1_g = (const float*)d_in[5];
    const float* ln1_b = (const float*)d_in[6];
    const float* ln2_g = (const float*)d_in[7];
    const float* ln2_b = (const float*)d_in[8];
    const float* w1    = (const float*)d_in[9];
    const float* b1    = (const float*)d_in[10];
    const float* w2    = (const float*)d_in[11];
    const float* b2    = (const float*)d_in[12];
    float* out = (float*)d_out;

    float *p_h, *p_qkv, *p_att, *p_x1, *p_mid;
    cudaGetSymbolAddress((void**)&p_h,   g_h);
    cudaGetSymbolAddress((void**)&p_qkv, g_qkv);
    cudaGetSymbolAddress((void**)&p_att, g_att);
    cudaGetSymbolAddress((void**)&p_x1,  g_x1);
    cudaGetSymbolAddress((void**)&p_mid, g_mid);

    // 1) h = LN1(x)
    ln_kernel<<<ROWS, 256>>>(x, ln1_g, ln1_b, p_h);

    // 2) qkv = h @ w_qkv + b_qkv              [4096 x 3072]
    gemm_kernel<0><<<dim3(3*DD/BN, ROWS/BM), 256>>>(p_h, w_qkv, b_qkv, nullptr,
                                                    p_qkv, ROWS, 3*DD, DD);

    // 3) causal attention -> g_att            [4096 x 1024]
    attn_kernel<<<dim3(TT/128, BB*HH), 128>>>();

    // 4) x1 = x + att @ w_fc + b_fc           [4096 x 1024]
    gemm_kernel<1><<<dim3(DD/BN, ROWS/BM), 256>>>(p_att, w_fc, b_fc, x,
                                                  p_x1, ROWS, DD, DD);

    // 5) h = LN2(x1)
    ln_kernel<<<ROWS, 256>>>(p_x1, ln2_g, ln2_b, p_h);

    // 6) mid = gelu(h @ w1 + b1)              [4096 x 4096]
    gemm_kernel<2><<<dim3(4*DD/BN, ROWS/BM), 256>>>(p_h, w1, b1, nullptr,
                                                    p_mid, ROWS, 4*DD, DD);

    // 7) out = x1 + mid @ w2 + b2             [4096 x 1024]
    gemm_kernel<1><<<dim3(DD/BN, ROWS/BM), 256>>>(p_mid, w2, b2, p_x1,
                                                  out, ROWS, DD, 4*DD);
}

// round 4
// speedup vs baseline: 1.8429x; 1.8429x over previous
#include <cuda_runtime.h>
#include <cuda_bf16.h>
#include <math.h>
#include <stdint.h>

// Problem constants
#define BB 2
#define TT 2048
#define DD 1024
#define HH 16
#define HD 64
#define ROWS (BB*TT)          // 4096

// ---------------- scratch (device globals; no allocations) ----------------
__device__ float g_h   [ROWS * DD];
__device__ float g_qkv [ROWS * 3 * DD];
__device__ float g_att [ROWS * DD];
__device__ float g_x1  [ROWS * DD];
__device__ float g_mid [ROWS * 4 * DD];

// ---------------- helpers -------------------------------------------------
__device__ __forceinline__ uint32_t smem_u32(const void* p) {
    uint32_t a;
    asm("{ .reg .u64 t; cvta.to.shared.u64 t, %1; cvt.u32.u64 %0, t; }"
        : "=r"(a) : "l"(p));
    return a;
}
__device__ __forceinline__ uint32_t f2tf(float f) {
    uint32_t u;
    asm("cvt.rna.tf32.f32 %0, %1;" : "=r"(u) : "f"(f));
    return u;
}
__device__ __forceinline__ void ldsm4(uint32_t& r0, uint32_t& r1,
                                      uint32_t& r2, uint32_t& r3, uint32_t a) {
    asm volatile("ldmatrix.sync.aligned.m8n8.x4.shared.b16 {%0,%1,%2,%3}, [%4];"
                 : "=r"(r0), "=r"(r1), "=r"(r2), "=r"(r3) : "r"(a));
}
__device__ __forceinline__ void mma8(float* c, const uint32_t* a, const uint32_t* b) {
    asm volatile(
        "mma.sync.aligned.m16n8k8.row.col.f32.tf32.tf32.f32 "
        "{%0,%1,%2,%3}, {%4,%5,%6,%7}, {%8,%9}, {%0,%1,%2,%3};"
        : "+f"(c[0]), "+f"(c[1]), "+f"(c[2]), "+f"(c[3])
        : "r"(a[0]), "r"(a[1]), "r"(a[2]), "r"(a[3]), "r"(b[0]), "r"(b[1]));
}
__device__ __forceinline__ float gelu_exact(float v) {
    return 0.5f * v * (1.0f + erff(v * 0.70710678118654752f));
}

// ---------------- LayerNorm ----------------------------------------------
__global__ void ln_kernel(const float* __restrict__ x,
                          const float* __restrict__ g,
                          const float* __restrict__ bvec,
                          float* __restrict__ out) {
    int row = blockIdx.x;
    int t   = threadIdx.x;
    const float4* xr = (const float4*)(x + (size_t)row * DD);
    float4 v = xr[t];
    float s  = v.x + v.y + v.z + v.w;
    float ss = v.x*v.x + v.y*v.y + v.z*v.z + v.w*v.w;
    #pragma unroll
    for (int o = 16; o > 0; o >>= 1) {
        s  += __shfl_xor_sync(0xffffffffu, s,  o);
        ss += __shfl_xor_sync(0xffffffffu, ss, o);
    }
    __shared__ float sh[2][8];
    int w = t >> 5, ln = t & 31;
    if (ln == 0) { sh[0][w] = s; sh[1][w] = ss; }
    __syncthreads();
    s = 0.f; ss = 0.f;
    #pragma unroll
    for (int i = 0; i < 8; i++) { s += sh[0][i]; ss += sh[1][i]; }
    float mu   = s * (1.0f / DD);
    float var  = ss * (1.0f / DD) - mu * mu;
    float rstd = rsqrtf(var + 1e-5f);
    float4 gg = ((const float4*)g)[t];
    float4 bb = ((const float4*)bvec)[t];
    float4 o4;
    o4.x = (v.x - mu) * rstd * gg.x + bb.x;
    o4.y = (v.y - mu) * rstd * gg.y + bb.y;
    o4.z = (v.z - mu) * rstd * gg.z + bb.z;
    o4.w = (v.w - mu) * rstd * gg.w + bb.w;
    ((float4*)(out + (size_t)row * DD))[t] = o4;
}

// ---------------- mma.sync tf32 GEMM --------------------------------------
// C[M,N] = A[M,K] @ B[K,N] (+bias / +residual / GELU)
// Tile 128x128, BK=32, 256 threads, warp grid 2(M)x4(N), warp tile 64x32.
// SMEM: A/B tiles stored as rows of 32 floats (8 quads of 16B) with XOR-quad
// swizzle quad^(row&7); B stored transposed [n][k]. ldmatrix.x4 b16 loads
// give exactly the tf32 m16n8k8 fragment layouts.
#define GBK 32
#define SMA0 0
#define SMA1 16384
#define SMB0 32768
#define SMB1 49152
#define GSMEM 65536

// EPI: 0 = +bias ; 1 = +bias + residual ; 2 = +bias then exact GELU
template <int EPI>
__global__ void __launch_bounds__(256)
gemm_mma(const float* __restrict__ A, const float* __restrict__ Bw,
         const float* __restrict__ bias, const float* __restrict__ res,
         float* __restrict__ C, int M, int N, int K) {
    extern __shared__ char smem[];
    const uint32_t sb = smem_u32(smem);
    const int tid  = threadIdx.x;
    const int wid  = tid >> 5;
    const int lane = tid & 31;
    const int m0 = blockIdx.y * 128;
    const int n0 = blockIdx.x * 128;
    const int warp_m = (wid & 1) * 64;
    const int warp_n = (wid >> 1) * 32;

    // ---- global load indexing ----
    const int ar = tid >> 3;            // A row 0..31 (+32*i)
    const int aq = tid & 7;             // A k-quad
    const int bkq = tid >> 5;           // B k-quad row group (0..7)
    const int bnq = tid & 31;           // B n-quad (0..31)

    const float* Abase = A + (size_t)(m0 + ar) * K + aq * 4;
    const float* Bbase = Bw + (size_t)(bkq * 4) * N + n0 + bnq * 4;

    // A store offsets: quad constant per thread = aq ^ (ar&7)
    const uint32_t aoff0 = (uint32_t)(ar * 128 + ((aq ^ (ar & 7)) * 16));

    float4 av[4];
    float4 bv[4];

    float acc[4][4][4];
    #pragma unroll
    for (int i = 0; i < 4; i++)
        #pragma unroll
        for (int j = 0; j < 4; j++)
            #pragma unroll
            for (int q = 0; q < 4; q++) acc[i][j][q] = 0.f;

    const int nch = K / GBK;

    // ldmatrix per-lane constants
    const int rowA = (lane & 7) + ((lane >> 3) & 1) * 8;   // 0..15
    const int qselA = lane >> 4;                           // 0/1
    const int lane7 = lane & 7;
    const int matB  = lane >> 3;                           // 0..3

    // ---- prologue: load+store chunk 0 ----
    {
        const float* ap = Abase;
        #pragma unroll
        for (int i = 0; i < 4; i++) av[i] = *(const float4*)(ap + (size_t)(i * 32) * K);
        const float* bp = Bbase;
        #pragma unroll
        for (int i = 0; i < 4; i++) bv[i] = *(const float4*)(bp + (size_t)i * N);
        // store A
        #pragma unroll
        for (int i = 0; i < 4; i++) {
            uint4 u = make_uint4(f2tf(av[i].x), f2tf(av[i].y), f2tf(av[i].z), f2tf(av[i].w));
            *(uint4*)(smem + SMA0 + aoff0 + i * 32 * 128) = u;
        }
        // store B transposed
        float wsx[4] = {bv[0].x, bv[1].x, bv[2].x, bv[3].x};
        float wsy[4] = {bv[0].y, bv[1].y, bv[2].y, bv[3].y};
        float wsz[4] = {bv[0].z, bv[1].z, bv[2].z, bv[3].z};
        float wsw[4] = {bv[0].w, bv[1].w, bv[2].w, bv[3].w};
        #pragma unroll
        for (int s = 0; s < 4; s++) {
            int j = (s + bnq) & 3;
            int n = bnq * 4 + j;
            uint32_t off = (uint32_t)(n * 128 + ((bkq ^ (n & 7)) * 16));
            float* col = (j == 0) ? wsx : (j == 1) ? wsy : (j == 2) ? wsz : wsw;
            uint4 u = make_uint4(f2tf(col[0]), f2tf(col[1]), f2tf(col[2]), f2tf(col[3]));
            *(uint4*)(smem + SMB0 + off) = u;
        }
    }
    __syncthreads();

    for (int c = 0; c < nch; c++) {
        const int buf = c & 1;
        const uint32_t As = sb + (buf ? SMA1 : SMA0);
        const uint32_t Bs = sb + (buf ? SMB1 : SMB0);

        // prefetch next chunk to registers
        if (c + 1 < nch) {
            const float* ap = Abase + (size_t)(c + 1) * GBK;
            #pragma unroll
            for (int i = 0; i < 4; i++) av[i] = *(const float4*)(ap + (size_t)(i * 32) * K);
            const float* bp = Bbase + (size_t)(c + 1) * GBK * N;
            #pragma unroll
            for (int i = 0; i < 4; i++) bv[i] = *(const float4*)(bp + (size_t)i * N);
        }

        // ---- compute on buf ----
        #pragma unroll
        for (int kb = 0; kb < 4; kb++) {
            uint32_t afr[4][4];
            uint32_t bfr[4][2];
            #pragma unroll
            for (int mb = 0; mb < 4; mb++) {
                int row = warp_m + mb * 16 + rowA;
                int quad = (2 * kb + qselA) ^ lane7;
                ldsm4(afr[mb][0], afr[mb][1], afr[mb][2], afr[mb][3],
                      As + (uint32_t)(row * 128 + quad * 16));
            }
            #pragma unroll
            for (int s = 0; s < 2; s++) {
                int nb = 2 * s + (matB >> 1);
                int n = warp_n + nb * 8 + lane7;
                int quad = (2 * kb + (matB & 1)) ^ lane7;
                ldsm4(bfr[2*s][0], bfr[2*s][1], bfr[2*s+1][0], bfr[2*s+1][1],
                      Bs + (uint32_t)(n * 128 + quad * 16));
            }
            #pragma unroll
            for (int mb = 0; mb < 4; mb++)
                #pragma unroll
                for (int nb = 0; nb < 4; nb++)
                    mma8(acc[mb][nb], afr[mb], bfr[nb]);
        }

        // ---- store prefetched chunk into other buffer ----
        if (c + 1 < nch) {
            const int ob = (c + 1) & 1;
            char* Asw = smem + (ob ? SMA1 : SMA0);
            char* Bsw = smem + (ob ? SMB1 : SMB0);
            #pragma unroll
            for (int i = 0; i < 4; i++) {
                uint4 u = make_uint4(f2tf(av[i].x), f2tf(av[i].y), f2tf(av[i].z), f2tf(av[i].w));
                *(uint4*)(Asw + aoff0 + i * 32 * 128) = u;
            }
            float wsx[4] = {bv[0].x, bv[1].x, bv[2].x, bv[3].x};
            float wsy[4] = {bv[0].y, bv[1].y, bv[2].y, bv[3].y};
            float wsz[4] = {bv[0].z, bv[1].z, bv[2].z, bv[3].z};
            float wsw[4] = {bv[0].w, bv[1].w, bv[2].w, bv[3].w};
            #pragma unroll
            for (int s = 0; s < 4; s++) {
                int j = (s + bnq) & 3;
                int n = bnq * 4 + j;
                uint32_t off = (uint32_t)(n * 128 + ((bkq ^ (n & 7)) * 16));
                float* col = (j == 0) ? wsx : (j == 1) ? wsy : (j == 2) ? wsz : wsw;
                uint4 u = make_uint4(f2tf(col[0]), f2tf(col[1]), f2tf(col[2]), f2tf(col[3]));
                *(uint4*)(Bsw + off) = u;
            }
        }
        __syncthreads();
    }

    // ---- epilogue ----
    const int gr = lane >> 2;          // 0..7
    const int cp = (lane & 3) * 2;     // col pair
    #pragma unroll
    for (int mb = 0; mb < 4; mb++) {
        #pragma unroll
        for (int nb = 0; nb < 4; nb++) {
            int row0 = m0 + warp_m + mb * 16 + gr;
            int col  = n0 + warp_n + nb * 8 + cp;
            float2 bi = *(const float2*)&bias[col];
            float v0 = acc[mb][nb][0] + bi.x;
            float v1 = acc[mb][nb][1] + bi.y;
            float v2 = acc[mb][nb][2] + bi.x;
            float v3 = acc[mb][nb][3] + bi.y;
            if (EPI == 1) {
                float2 r0 = *(const float2*)&res[(size_t)row0 * N + col];
                float2 r1 = *(const float2*)&res[(size_t)(row0 + 8) * N + col];
                v0 += r0.x; v1 += r0.y; v2 += r1.x; v3 += r1.y;
            }
            if (EPI == 2) {
                v0 = gelu_exact(v0); v1 = gelu_exact(v1);
                v2 = gelu_exact(v2); v3 = gelu_exact(v3);
            }
            *(float2*)&C[(size_t)row0 * N + col]       = make_float2(v0, v1);
            *(float2*)&C[(size_t)(row0 + 8) * N + col] = make_float2(v2, v3);
        }
    }
}

// ---------------- Attention: causal flash, 1 thread = 1 query row ---------
__global__ void __launch_bounds__(128)
attn_kernel() {
    int qblk = blockIdx.x;
    int bh   = blockIdx.y;
    int b = bh >> 4;
    int h = bh & 15;
    int r = threadIdx.x;
    int qi = qblk * 128 + r;

    const float* base = g_qkv + (size_t)b * TT * 3 * DD;

    float q[HD];
    {
        const float4* qp = (const float4*)(base + (size_t)qi * 3 * DD + h * HD);
        #pragma unroll
        for (int d4 = 0; d4 < HD / 4; d4++) {
            float4 v = qp[d4];
            q[d4*4+0] = v.x * 0.125f;
            q[d4*4+1] = v.y * 0.125f;
            q[d4*4+2] = v.z * 0.125f;
            q[d4*4+3] = v.w * 0.125f;
        }
    }

    float o[HD];
    #pragma unroll
    for (int d = 0; d < HD; d++) o[d] = 0.f;
    float m = -1e30f, l = 0.f;

    __shared__ float Ks[64][HD];
    __shared__ float Vs[64][HD];

    int kmax = qblk * 128 + 127;
    int lr = r >> 1;
    int lc = (r & 1) * 32;

    for (int kb = 0; kb * 64 <= kmax; kb++) {
        const float4* kp = (const float4*)(base + (size_t)(kb*64 + lr) * 3 * DD + DD + h * HD + lc);
        const float4* vp = (const float4*)(base + (size_t)(kb*64 + lr) * 3 * DD + 2*DD + h * HD + lc);
        #pragma unroll
        for (int i = 0; i < 8; i++) {
            ((float4*)&Ks[lr][lc])[i] = kp[i];
            ((float4*)&Vs[lr][lc])[i] = vp[i];
        }
        __syncthreads();

        int jend = qi - kb * 64 + 1;
        if (jend > 64) jend = 64;
        for (int j = 0; j < jend; j++) {
            float s = 0.f;
            const float4* kr = (const float4*)Ks[j];
            #pragma unroll
            for (int d4 = 0; d4 < HD / 4; d4++) {
                float4 kv = kr[d4];
                s += q[d4*4+0]*kv.x + q[d4*4+1]*kv.y + q[d4*4+2]*kv.z + q[d4*4+3]*kv.w;
            }
            if (s > m) {
                float sc = __expf(m - s);
                m = s;
                l *= sc;
                #pragma unroll
                for (int d = 0; d < HD; d++) o[d] *= sc;
            }
            float p = __expf(s - m);
            l += p;
            const float4* vr = (const float4*)Vs[j];
            #pragma unroll
            for (int d4 = 0; d4 < HD / 4; d4++) {
                float4 vv = vr[d4];
                o[d4*4+0] += p * vv.x;
                o[d4*4+1] += p * vv.y;
                o[d4*4+2] += p * vv.z;
                o[d4*4+3] += p * vv.w;
            }
        }
        __syncthreads();
    }

    float inv = 1.0f / l;
    float4* op = (float4*)(g_att + ((size_t)b * TT + qi) * DD + h * HD);
    #pragma unroll
    for (int d4 = 0; d4 < HD / 4; d4++) {
        float4 v;
        v.x = o[d4*4+0] * inv;
        v.y = o[d4*4+1] * inv;
        v.z = o[d4*4+2] * inv;
        v.w = o[d4*4+3] * inv;
        op[d4] = v;
    }
}

// ---------------- launch -------------------------------------------------
extern "C" void kernel_launch(void* const* d_in, const int* in_sizes, int n_in,
                              void* d_out, int out_size) {
    const float* x     = (const float*)d_in[0];
    const float* w_qkv = (const float*)d_in[1];
    const float* b_qkv = (const float*)d_in[2];
    const float* w_fc  = (const float*)d_in[3];
    const float* b_fc  = (const float*)d_in[4];
    const float* ln1_g = (const float*)d_in[5];
    const float* ln1_b = (const float*)d_in[6];
    const float* ln2_g = (const float*)d_in[7];
    const float* ln2_b = (const float*)d_in[8];
    const float* w1    = (const float*)d_in[9];
    const float* b1    = (const float*)d_in[10];
    const float* w2    = (const float*)d_in[11];
    const float* b2    = (const float*)d_in[12];
    float* out = (float*)d_out;

    float *p_h, *p_qkv, *p_att, *p_x1, *p_mid;
    cudaGetSymbolAddress((void**)&p_h,   g_h);
    cudaGetSymbolAddress((void**)&p_qkv, g_qkv);
    cudaGetSymbolAddress((void**)&p_att, g_att);
    cudaGetSymbolAddress((void**)&p_x1,  g_x1);
    cudaGetSymbolAddress((void**)&p_mid, g_mid);

    cudaFuncSetAttribute(gemm_mma<0>, cudaFuncAttributeMaxDynamicSharedMemorySize, GSMEM);
    cudaFuncSetAttribute(gemm_mma<1>, cudaFuncAttributeMaxDynamicSharedMemorySize, GSMEM);
    cudaFuncSetAttribute(gemm_mma<2>, cudaFuncAttributeMaxDynamicSharedMemorySize, GSMEM);

    // 1) h = LN1(x)
    ln_kernel<<<ROWS, 256>>>(x, ln1_g, ln1_b, p_h);

    // 2) qkv = h @ w_qkv + b_qkv              [4096 x 3072]
    gemm_mma<0><<<dim3(3*DD/128, ROWS/128), 256, GSMEM>>>(
        p_h, w_qkv, b_qkv, nullptr, p_qkv, ROWS, 3*DD, DD);

    // 3) causal attention -> g_att            [4096 x 1024]
    attn_kernel<<<dim3(TT/128, BB*HH), 128>>>();

    // 4) x1 = x + att @ w_fc + b_fc           [4096 x 1024]
    gemm_mma<1><<<dim3(DD/128, ROWS/128), 256, GSMEM>>>(
        p_att, w_fc, b_fc, x, p_x1, ROWS, DD, DD);

    // 5) h = LN2(x1)
    ln_kernel<<<ROWS, 256>>>(p_x1, ln2_g, ln2_b, p_h);

    // 6) mid = gelu(h @ w1 + b1)              [4096 x 4096]
    gemm_mma<2><<<dim3(4*DD/128, ROWS/128), 256, GSMEM>>>(
        p_h, w1, b1, nullptr, p_mid, ROWS, 4*DD, DD);

    // 7) out = x1 + mid @ w2 + b2             [4096 x 1024]
    gemm_mma<1><<<dim3(DD/128, ROWS/128), 256, GSMEM>>>(
        p_mid, w2, b2, p_x1, out, ROWS, DD, 4*DD);
}

// round 5
// speedup vs baseline: 3.1103x; 1.6877x over previous
#include <cuda_runtime.h>
#include <cuda_bf16.h>
#include <math.h>
#include <stdint.h>

// Problem constants
#define BB 2
#define TT 2048
#define DD 1024
#define HH 16
#define HD 64
#define ROWS (BB*TT)          // 4096

// ---------------- scratch (device globals; no allocations) ----------------
__device__ float g_h   [ROWS * DD];
__device__ float g_qkv [ROWS * 3 * DD];
__device__ float g_att [ROWS * DD];
__device__ float g_x1  [ROWS * DD];
__device__ float g_mid [ROWS * 4 * DD];

// ---------------- helpers -------------------------------------------------
__device__ __forceinline__ uint32_t smem_u32(const void* p) {
    uint32_t a;
    asm("{ .reg .u64 t; cvta.to.shared.u64 t, %1; cvt.u32.u64 %0, t; }"
        : "=r"(a) : "l"(p));
    return a;
}
__device__ __forceinline__ uint32_t f2tf(float f) {
    uint32_t u;
    asm("cvt.rna.tf32.f32 %0, %1;" : "=r"(u) : "f"(f));
    return u;
}
__device__ __forceinline__ void ldsm4(uint32_t& r0, uint32_t& r1,
                                      uint32_t& r2, uint32_t& r3, uint32_t a) {
    asm volatile("ldmatrix.sync.aligned.m8n8.x4.shared.b16 {%0,%1,%2,%3}, [%4];"
                 : "=r"(r0), "=r"(r1), "=r"(r2), "=r"(r3) : "r"(a));
}
__device__ __forceinline__ void mma8(float* c, const uint32_t* a, const uint32_t* b) {
    asm volatile(
        "mma.sync.aligned.m16n8k8.row.col.f32.tf32.tf32.f32 "
        "{%0,%1,%2,%3}, {%4,%5,%6,%7}, {%8,%9}, {%0,%1,%2,%3};"
        : "+f"(c[0]), "+f"(c[1]), "+f"(c[2]), "+f"(c[3])
        : "r"(a[0]), "r"(a[1]), "r"(a[2]), "r"(a[3]), "r"(b[0]), "r"(b[1]));
}
__device__ __forceinline__ float gelu_exact(float v) {
    return 0.5f * v * (1.0f + erff(v * 0.70710678118654752f));
}

// ---------------- LayerNorm ----------------------------------------------
__global__ void ln_kernel(const float* __restrict__ x,
                          const float* __restrict__ g,
                          const float* __restrict__ bvec,
                          float* __restrict__ out) {
    int row = blockIdx.x;
    int t   = threadIdx.x;
    const float4* xr = (const float4*)(x + (size_t)row * DD);
    float4 v = xr[t];
    float s  = v.x + v.y + v.z + v.w;
    float ss = v.x*v.x + v.y*v.y + v.z*v.z + v.w*v.w;
    #pragma unroll
    for (int o = 16; o > 0; o >>= 1) {
        s  += __shfl_xor_sync(0xffffffffu, s,  o);
        ss += __shfl_xor_sync(0xffffffffu, ss, o);
    }
    __shared__ float sh[2][8];
    int w = t >> 5, ln = t & 31;
    if (ln == 0) { sh[0][w] = s; sh[1][w] = ss; }
    __syncthreads();
    s = 0.f; ss = 0.f;
    #pragma unroll
    for (int i = 0; i < 8; i++) { s += sh[0][i]; ss += sh[1][i]; }
    float mu   = s * (1.0f / DD);
    float var  = ss * (1.0f / DD) - mu * mu;
    float rstd = rsqrtf(var + 1e-5f);
    float4 gg = ((const float4*)g)[t];
    float4 bb = ((const float4*)bvec)[t];
    float4 o4;
    o4.x = (v.x - mu) * rstd * gg.x + bb.x;
    o4.y = (v.y - mu) * rstd * gg.y + bb.y;
    o4.z = (v.z - mu) * rstd * gg.z + bb.z;
    o4.w = (v.w - mu) * rstd * gg.w + bb.w;
    ((float4*)(out + (size_t)row * DD))[t] = o4;
}

// ---------------- mma.sync tf32 GEMM (unchanged from R4) ------------------
#define GBK 32
#define SMA0 0
#define SMA1 16384
#define SMB0 32768
#define SMB1 49152
#define GSMEM 65536

template <int EPI>
__global__ void __launch_bounds__(256)
gemm_mma(const float* __restrict__ A, const float* __restrict__ Bw,
         const float* __restrict__ bias, const float* __restrict__ res,
         float* __restrict__ C, int M, int N, int K) {
    extern __shared__ char smem[];
    const uint32_t sb = smem_u32(smem);
    const int tid  = threadIdx.x;
    const int wid  = tid >> 5;
    const int lane = tid & 31;
    const int m0 = blockIdx.y * 128;
    const int n0 = blockIdx.x * 128;
    const int warp_m = (wid & 1) * 64;
    const int warp_n = (wid >> 1) * 32;

    const int ar = tid >> 3;
    const int aq = tid & 7;
    const int bkq = tid >> 5;
    const int bnq = tid & 31;

    const float* Abase = A + (size_t)(m0 + ar) * K + aq * 4;
    const float* Bbase = Bw + (size_t)(bkq * 4) * N + n0 + bnq * 4;

    const uint32_t aoff0 = (uint32_t)(ar * 128 + ((aq ^ (ar & 7)) * 16));

    float4 av[4];
    float4 bv[4];

    float acc[4][4][4];
    #pragma unroll
    for (int i = 0; i < 4; i++)
        #pragma unroll
        for (int j = 0; j < 4; j++)
            #pragma unroll
            for (int q = 0; q < 4; q++) acc[i][j][q] = 0.f;

    const int nch = K / GBK;

    const int rowA = (lane & 7) + ((lane >> 3) & 1) * 8;
    const int qselA = lane >> 4;
    const int lane7 = lane & 7;
    const int matB  = lane >> 3;

    {
        const float* ap = Abase;
        #pragma unroll
        for (int i = 0; i < 4; i++) av[i] = *(const float4*)(ap + (size_t)(i * 32) * K);
        const float* bp = Bbase;
        #pragma unroll
        for (int i = 0; i < 4; i++) bv[i] = *(const float4*)(bp + (size_t)i * N);
        #pragma unroll
        for (int i = 0; i < 4; i++) {
            uint4 u = make_uint4(f2tf(av[i].x), f2tf(av[i].y), f2tf(av[i].z), f2tf(av[i].w));
            *(uint4*)(smem + SMA0 + aoff0 + i * 32 * 128) = u;
        }
        float wsx[4] = {bv[0].x, bv[1].x, bv[2].x, bv[3].x};
        float wsy[4] = {bv[0].y, bv[1].y, bv[2].y, bv[3].y};
        float wsz[4] = {bv[0].z, bv[1].z, bv[2].z, bv[3].z};
        float wsw[4] = {bv[0].w, bv[1].w, bv[2].w, bv[3].w};
        #pragma unroll
        for (int s = 0; s < 4; s++) {
            int j = (s + bnq) & 3;
            int n = bnq * 4 + j;
            uint32_t off = (uint32_t)(n * 128 + ((bkq ^ (n & 7)) * 16));
            float* col = (j == 0) ? wsx : (j == 1) ? wsy : (j == 2) ? wsz : wsw;
            uint4 u = make_uint4(f2tf(col[0]), f2tf(col[1]), f2tf(col[2]), f2tf(col[3]));
            *(uint4*)(smem + SMB0 + off) = u;
        }
    }
    __syncthreads();

    for (int c = 0; c < nch; c++) {
        const int buf = c & 1;
        const uint32_t As = sb + (buf ? SMA1 : SMA0);
        const uint32_t Bs = sb + (buf ? SMB1 : SMB0);

        if (c + 1 < nch) {
            const float* ap = Abase + (size_t)(c + 1) * GBK;
            #pragma unroll
            for (int i = 0; i < 4; i++) av[i] = *(const float4*)(ap + (size_t)(i * 32) * K);
            const float* bp = Bbase + (size_t)(c + 1) * GBK * N;
            #pragma unroll
            for (int i = 0; i < 4; i++) bv[i] = *(const float4*)(bp + (size_t)i * N);
        }

        #pragma unroll
        for (int kb = 0; kb < 4; kb++) {
            uint32_t afr[4][4];
            uint32_t bfr[4][2];
            #pragma unroll
            for (int mb = 0; mb < 4; mb++) {
                int row = warp_m + mb * 16 + rowA;
                int quad = (2 * kb + qselA) ^ lane7;
                ldsm4(afr[mb][0], afr[mb][1], afr[mb][2], afr[mb][3],
                      As + (uint32_t)(row * 128 + quad * 16));
            }
            #pragma unroll
            for (int s = 0; s < 2; s++) {
                int nb = 2 * s + (matB >> 1);
                int n = warp_n + nb * 8 + lane7;
                int quad = (2 * kb + (matB & 1)) ^ lane7;
                ldsm4(bfr[2*s][0], bfr[2*s][1], bfr[2*s+1][0], bfr[2*s+1][1],
                      Bs + (uint32_t)(n * 128 + quad * 16));
            }
            #pragma unroll
            for (int mb = 0; mb < 4; mb++)
                #pragma unroll
                for (int nb = 0; nb < 4; nb++)
                    mma8(acc[mb][nb], afr[mb], bfr[nb]);
        }

        if (c + 1 < nch) {
            const int ob = (c + 1) & 1;
            char* Asw = smem + (ob ? SMA1 : SMA0);
            char* Bsw = smem + (ob ? SMB1 : SMB0);
            #pragma unroll
            for (int i = 0; i < 4; i++) {
                uint4 u = make_uint4(f2tf(av[i].x), f2tf(av[i].y), f2tf(av[i].z), f2tf(av[i].w));
                *(uint4*)(Asw + aoff0 + i * 32 * 128) = u;
            }
            float wsx[4] = {bv[0].x, bv[1].x, bv[2].x, bv[3].x};
            float wsy[4] = {bv[0].y, bv[1].y, bv[2].y, bv[3].y};
            float wsz[4] = {bv[0].z, bv[1].z, bv[2].z, bv[3].z};
            float wsw[4] = {bv[0].w, bv[1].w, bv[2].w, bv[3].w};
            #pragma unroll
            for (int s = 0; s < 4; s++) {
                int j = (s + bnq) & 3;
                int n = bnq * 4 + j;
                uint32_t off = (uint32_t)(n * 128 + ((bkq ^ (n & 7)) * 16));
                float* col = (j == 0) ? wsx : (j == 1) ? wsy : (j == 2) ? wsz : wsw;
                uint4 u = make_uint4(f2tf(col[0]), f2tf(col[1]), f2tf(col[2]), f2tf(col[3]));
                *(uint4*)(Bsw + off) = u;
            }
        }
        __syncthreads();
    }

    const int gr = lane >> 2;
    const int cp = (lane & 3) * 2;
    #pragma unroll
    for (int mb = 0; mb < 4; mb++) {
        #pragma unroll
        for (int nb = 0; nb < 4; nb++) {
            int row0 = m0 + warp_m + mb * 16 + gr;
            int col  = n0 + warp_n + nb * 8 + cp;
            float2 bi = *(const float2*)&bias[col];
            float v0 = acc[mb][nb][0] + bi.x;
            float v1 = acc[mb][nb][1] + bi.y;
            float v2 = acc[mb][nb][2] + bi.x;
            float v3 = acc[mb][nb][3] + bi.y;
            if (EPI == 1) {
                float2 r0 = *(const float2*)&res[(size_t)row0 * N + col];
                float2 r1 = *(const float2*)&res[(size_t)(row0 + 8) * N + col];
                v0 += r0.x; v1 += r0.y; v2 += r1.x; v3 += r1.y;
            }
            if (EPI == 2) {
                v0 = gelu_exact(v0); v1 = gelu_exact(v1);
                v2 = gelu_exact(v2); v3 = gelu_exact(v3);
            }
            *(float2*)&C[(size_t)row0 * N + col]       = make_float2(v0, v1);
            *(float2*)&C[(size_t)(row0 + 8) * N + col] = make_float2(v2, v3);
        }
    }
}

// ---------------- tensor-core flash attention -----------------------------
// CTA: 128 queries of one (b,h). 8 warps, warp grid 4(M)x2(N).
// SMEM buffers (bytes): Qlo 0, Qhi 16K, Klo 32K, Khi 48K,
//   Vt 64K..96K (4 bufs of 8K: [hd64][key32]), P 96K..160K (4 bufs of 16K),
//   sm_m 160K (2*128 f), sm_s +1K. Total 165888.
#define AQLO 0
#define AQHI 16384
#define AKLO 32768
#define AKHI 49152
#define AVT  65536
#define APS  98304
#define ASMM 163840
#define ASMS 164864
#define ATT_SMEM 165888

__global__ void __launch_bounds__(256)
attn_mma() {
    extern __shared__ char smem[];
    const uint32_t sb = smem_u32(smem);
    float* smf = (float*)smem;

    const int qblk = gridDim.x - 1 - blockIdx.x;   // long CTAs first
    const int bh = blockIdx.y;
    const int b = bh >> 4, h = bh & 15;
    const int q0 = qblk * 128;

    const float* base = g_qkv + (size_t)b * TT * 3 * DD;
    const float* qb = base + h * HD;
    const float* kb_ = base + DD + h * HD;
    const float* vb = base + 2 * DD + h * HD;

    const int tid = threadIdx.x, wid = tid >> 5, lane = tid & 31;
    const int gr = lane >> 2, qd = lane & 3;
    const int warp_m  = (wid & 3) * 32;
    const int warp_ns = (wid >> 2) * 64;
    const int warp_np = (wid >> 2) * 32;
    const int slot = wid >> 2;

    const int rowA = (lane & 7) + ((lane >> 3) & 1) * 8;
    const int qselA = lane >> 4;
    const int lane7 = lane & 7, matB = lane >> 3;

    // ---- load Q tile (scaled by 1/sqrt(64)=0.125), tf32, swizzled ----
    #pragma unroll
    for (int i = 0; i < 8; i++) {
        int idx = tid + i * 256;
        int r = idx >> 4, c4 = idx & 15;
        float4 v = *(const float4*)(qb + (size_t)(q0 + r) * 3 * DD + c4 * 4);
        uint32_t off = (c4 < 8 ? AQLO : AQHI) +
                       (uint32_t)(r * 128 + (((c4 & 7) ^ (r & 7)) * 16));
        uint4 u = make_uint4(f2tf(v.x * 0.125f), f2tf(v.y * 0.125f),
                             f2tf(v.z * 0.125f), f2tf(v.w * 0.125f));
        *(uint4*)(smem + off) = u;
    }

    float m_old[4], lsum[4];
    #pragma unroll
    for (int i = 0; i < 4; i++) { m_old[i] = -1e30f; lsum[i] = 0.f; }
    float o[2][4][4];
    #pragma unroll
    for (int mb = 0; mb < 2; mb++)
        #pragma unroll
        for (int nb = 0; nb < 4; nb++)
            #pragma unroll
            for (int q = 0; q < 4; q++) o[mb][nb][q] = 0.f;

    // row_local per stat slot i = mb*2+half
    int rloc[4];
    #pragma unroll
    for (int i = 0; i < 4; i++)
        rloc[i] = warp_m + (i >> 1) * 16 + (i & 1) * 8 + gr;

    for (int kt = 0; kt <= qblk; kt++) {
        __syncthreads();   // prior tile's ldmatrix reads done; Q visible (1st iter)

        // ---- K tile load ----
        #pragma unroll
        for (int i = 0; i < 8; i++) {
            int idx = tid + i * 256;
            int r = idx >> 4, c4 = idx & 15;
            float4 v = *(const float4*)(kb_ + (size_t)(kt * 128 + r) * 3 * DD + c4 * 4);
            uint32_t off = (c4 < 8 ? AKLO : AKHI) +
                           (uint32_t)(r * 128 + (((c4 & 7) ^ (r & 7)) * 16));
            *(uint4*)(smem + off) = make_uint4(f2tf(v.x), f2tf(v.y), f2tf(v.z), f2tf(v.w));
        }
        // ---- V tile load + transpose to Vt[hd][key] ----
        #pragma unroll
        for (int i = 0; i < 2; i++) {
            int lin = tid + i * 256;
            int kq = lin & 31, hq = lin >> 5;
            const float* vp = vb + (size_t)(kt * 128 + kq * 4) * 3 * DD + hq * 4;
            float4 r0 = *(const float4*)(vp);
            float4 r1 = *(const float4*)(vp + 3 * DD);
            float4 r2 = *(const float4*)(vp + 6 * DD);
            float4 r3 = *(const float4*)(vp + 9 * DD);
            float wsx[4] = {r0.x, r1.x, r2.x, r3.x};
            float wsy[4] = {r0.y, r1.y, r2.y, r3.y};
            float wsz[4] = {r0.z, r1.z, r2.z, r3.z};
            float wsw[4] = {r0.w, r1.w, r2.w, r3.w};
            #pragma unroll
            for (int s = 0; s < 4; s++) {
                int t = (s + kq) & 3;
                int hd = hq * 4 + t;
                float* col = (t == 0) ? wsx : (t == 1) ? wsy : (t == 2) ? wsz : wsw;
                uint32_t off = AVT + (kq >> 3) * 8192 +
                               (uint32_t)(hd * 128 + (((kq & 7) ^ (hd & 7)) * 16));
                *(uint4*)(smem + off) =
                    make_uint4(f2tf(col[0]), f2tf(col[1]), f2tf(col[2]), f2tf(col[3]));
            }
        }
        __syncthreads();

        // ---- S = Q @ K^T  (warp tile 32x64) ----
        float sacc[2][8][4];
        #pragma unroll
        for (int mb = 0; mb < 2; mb++)
            #pragma unroll
            for (int nb = 0; nb < 8; nb++)
                #pragma unroll
                for (int q = 0; q < 4; q++) sacc[mb][nb][q] = 0.f;

        #pragma unroll
        for (int kb = 0; kb < 8; kb++) {
            const uint32_t Ab = sb + (kb < 4 ? AQLO : AQHI);
            const uint32_t Bb = sb + (kb < 4 ? AKLO : AKHI);
            const int ks = kb & 3;
            uint32_t afr[2][4], bfr[8][2];
            #pragma unroll
            for (int mb = 0; mb < 2; mb++) {
                int row = warp_m + mb * 16 + rowA;
                int quad = (2 * ks + qselA) ^ (rowA & 7);
                ldsm4(afr[mb][0], afr[mb][1], afr[mb][2], afr[mb][3],
                      Ab + (uint32_t)(row * 128 + quad * 16));
            }
            #pragma unroll
            for (int s = 0; s < 4; s++) {
                int nb = 2 * s + (matB >> 1);
                int n = warp_ns + nb * 8 + lane7;
                int quad = (2 * ks + (matB & 1)) ^ lane7;
                ldsm4(bfr[2*s][0], bfr[2*s][1], bfr[2*s+1][0], bfr[2*s+1][1],
                      Bb + (uint32_t)(n * 128 + quad * 16));
            }
            #pragma unroll
            for (int mb = 0; mb < 2; mb++)
                #pragma unroll
                for (int nb = 0; nb < 8; nb++)
                    mma8(sacc[mb][nb], afr[mb], bfr[nb]);
        }

        // ---- causal mask (diagonal tile only) ----
        if (kt == qblk) {
            #pragma unroll
            for (int mb = 0; mb < 2; mb++)
                #pragma unroll
                for (int half = 0; half < 2; half++) {
                    int rowg = q0 + rloc[mb * 2 + half];
                    #pragma unroll
                    for (int nb = 0; nb < 8; nb++)
                        #pragma unroll
                        for (int j = 0; j < 2; j++) {
                            int col = kt * 128 + warp_ns + nb * 8 + 2 * qd + j;
                            if (col > rowg) sacc[mb][nb][half * 2 + j] = -1e30f;
                        }
                }
        }

        // ---- row max (warp) ----
        float mt[4];
        #pragma unroll
        for (int i = 0; i < 4; i++) {
            int mb = i >> 1, half = i & 1;
            float v = -1e30f;
            #pragma unroll
            for (int nb = 0; nb < 8; nb++) {
                v = fmaxf(v, sacc[mb][nb][half * 2 + 0]);
                v = fmaxf(v, sacc[mb][nb][half * 2 + 1]);
            }
            v = fmaxf(v, __shfl_xor_sync(0xffffffffu, v, 1));
            v = fmaxf(v, __shfl_xor_sync(0xffffffffu, v, 2));
            mt[i] = v;
        }
        if (qd == 0) {
            #pragma unroll
            for (int i = 0; i < 4; i++)
                smf[(ASMM >> 2) + slot * 128 + rloc[i]] = mt[i];
        }
        __syncthreads();

        float mnew[4], sc[4];
        #pragma unroll
        for (int i = 0; i < 4; i++) {
            float mfull = fmaxf(smf[(ASMM >> 2) + rloc[i]],
                                smf[(ASMM >> 2) + 128 + rloc[i]]);
            mnew[i] = fmaxf(m_old[i], mfull);
            sc[i] = __expf(m_old[i] - mnew[i]);
            m_old[i] = mnew[i];
        }

        // ---- P = exp(S - m), row sums ----
        float ts[4] = {0.f, 0.f, 0.f, 0.f};
        #pragma unroll
        for (int mb = 0; mb < 2; mb++)
            #pragma unroll
            for (int half = 0; half < 2; half++) {
                int i = mb * 2 + half;
                #pragma unroll
                for (int nb = 0; nb < 8; nb++) {
                    float p0 = __expf(sacc[mb][nb][half * 2 + 0] - mnew[i]);
                    float p1 = __expf(sacc[mb][nb][half * 2 + 1] - mnew[i]);
                    sacc[mb][nb][half * 2 + 0] = p0;
                    sacc[mb][nb][half * 2 + 1] = p1;
                    ts[i] += p0 + p1;
                }
            }
        #pragma unroll
        for (int i = 0; i < 4; i++) {
            ts[i] += __shfl_xor_sync(0xffffffffu, ts[i], 1);
            ts[i] += __shfl_xor_sync(0xffffffffu, ts[i], 2);
        }
        if (qd == 0) {
            #pragma unroll
            for (int i = 0; i < 4; i++)
                smf[(ASMS >> 2) + slot * 128 + rloc[i]] = ts[i];
        }
        // rescale O and l by sc while sums land
        #pragma unroll
        for (int mb = 0; mb < 2; mb++)
            #pragma unroll
            for (int nb = 0; nb < 4; nb++) {
                o[mb][nb][0] *= sc[mb * 2 + 0];
                o[mb][nb][1] *= sc[mb * 2 + 0];
                o[mb][nb][2] *= sc[mb * 2 + 1];
                o[mb][nb][3] *= sc[mb * 2 + 1];
            }
        #pragma unroll
        for (int i = 0; i < 4; i++) lsum[i] *= sc[i];
        __syncthreads();
        #pragma unroll
        for (int i = 0; i < 4; i++)
            lsum[i] += smf[(ASMS >> 2) + rloc[i]] + smf[(ASMS >> 2) + 128 + rloc[i]];

        // ---- store P (tf32) to SMEM ----
        #pragma unroll
        for (int mb = 0; mb < 2; mb++)
            #pragma unroll
            for (int half = 0; half < 2; half++) {
                int row = rloc[mb * 2 + half];
                #pragma unroll
                for (int nb = 0; nb < 8; nb++) {
                    int col0 = warp_ns + nb * 8 + 2 * qd;
                    int cbuf = col0 >> 5, c5 = col0 & 31;
                    uint32_t addr = APS + cbuf * 16384 +
                        (uint32_t)(row * 128 + (((c5 >> 2) ^ (row & 7)) * 16) + (c5 & 3) * 4);
                    uint2 u = make_uint2(f2tf(sacc[mb][nb][half * 2 + 0]),
                                         f2tf(sacc[mb][nb][half * 2 + 1]));
                    *(uint2*)(smem + addr) = u;
                }
            }
        __syncthreads();

        // ---- O += P @ V  (warp tile 32x32, k = 128 keys) ----
        #pragma unroll
        for (int ksx = 0; ksx < 16; ksx++) {
            const uint32_t Pb = sb + APS + (ksx >> 2) * 16384;
            const uint32_t Vb = sb + AVT + (ksx >> 2) * 8192;
            const int kk = ksx & 3;
            uint32_t afr[2][4], bfr[4][2];
            #pragma unroll
            for (int mb = 0; mb < 2; mb++) {
                int row = warp_m + mb * 16 + rowA;
                int quad = (2 * kk + qselA) ^ (rowA & 7);
                ldsm4(afr[mb][0], afr[mb][1], afr[mb][2], afr[mb][3],
                      Pb + (uint32_t)(row * 128 + quad * 16));
            }
            #pragma unroll
            for (int s = 0; s < 2; s++) {
                int nb = 2 * s + (matB >> 1);
                int n = warp_np + nb * 8 + lane7;
                int quad = (2 * kk + (matB & 1)) ^ lane7;
                ldsm4(bfr[2*s][0], bfr[2*s][1], bfr[2*s+1][0], bfr[2*s+1][1],
                      Vb + (uint32_t)(n * 128 + quad * 16));
            }
            #pragma unroll
            for (int mb = 0; mb < 2; mb++)
                #pragma unroll
                for (int nb = 0; nb < 4; nb++)
                    mma8(o[mb][nb], afr[mb], bfr[nb]);
        }
    }

    // ---- normalize + write ----
    float inv[4];
    #pragma unroll
    for (int i = 0; i < 4; i++) inv[i] = 1.0f / lsum[i];
    #pragma unroll
    for (int mb = 0; mb < 2; mb++)
        #pragma unroll
        for (int half = 0; half < 2; half++) {
            int i = mb * 2 + half;
            int row = q0 + rloc[i];
            #pragma unroll
            for (int nb = 0; nb < 4; nb++) {
                int col = warp_np + nb * 8 + 2 * qd;
                float2 w = make_float2(o[mb][nb][half * 2 + 0] * inv[i],
                                       o[mb][nb][half * 2 + 1] * inv[i]);
                *(float2*)&g_att[((size_t)b * TT + row) * DD + h * HD + col] = w;
            }
        }
}

// ---------------- launch -------------------------------------------------
extern "C" void kernel_launch(void* const* d_in, const int* in_sizes, int n_in,
                              void* d_out, int out_size) {
    const float* x     = (const float*)d_in[0];
    const float* w_qkv = (const float*)d_in[1];
    const float* b_qkv = (const float*)d_in[2];
    const float* w_fc  = (const float*)d_in[3];
    const float* b_fc  = (const float*)d_in[4];
    const float* ln1_g = (const float*)d_in[5];
    const float* ln1_b = (const float*)d_in[6];
    const float* ln2_g = (const float*)d_in[7];
    const float* ln2_b = (const float*)d_in[8];
    const float* w1    = (const float*)d_in[9];
    const float* b1    = (const float*)d_in[10];
    const float* w2    = (const float*)d_in[11];
    const float* b2    = (const float*)d_in[12];
    float* out = (float*)d_out;

    float *p_h, *p_qkv, *p_att, *p_x1, *p_mid;
    cudaGetSymbolAddress((void**)&p_h,   g_h);
    cudaGetSymbolAddress((void**)&p_qkv, g_qkv);
    cudaGetSymbolAddress((void**)&p_att, g_att);
    cudaGetSymbolAddress((void**)&p_x1,  g_x1);
    cudaGetSymbolAddress((void**)&p_mid, g_mid);

    cudaFuncSetAttribute(gemm_mma<0>, cudaFuncAttributeMaxDynamicSharedMemorySize, GSMEM);
    cudaFuncSetAttribute(gemm_mma<1>, cudaFuncAttributeMaxDynamicSharedMemorySize, GSMEM);
    cudaFuncSetAttribute(gemm_mma<2>, cudaFuncAttributeMaxDynamicSharedMemorySize, GSMEM);
    cudaFuncSetAttribute(attn_mma,    cudaFuncAttributeMaxDynamicSharedMemorySize, ATT_SMEM);

    // 1) h = LN1(x)
    ln_kernel<<<ROWS, 256>>>(x, ln1_g, ln1_b, p_h);

    // 2) qkv = h @ w_qkv + b_qkv              [4096 x 3072]
    gemm_mma<0><<<dim3(3*DD/128, ROWS/128), 256, GSMEM>>>(
        p_h, w_qkv, b_qkv, nullptr, p_qkv, ROWS, 3*DD, DD);

    // 3) causal attention -> g_att            [4096 x 1024]
    attn_mma<<<dim3(TT/128, BB*HH), 256, ATT_SMEM>>>();

    // 4) x1 = x + att @ w_fc + b_fc           [4096 x 1024]
    gemm_mma<1><<<dim3(DD/128, ROWS/128), 256, GSMEM>>>(
        p_att, w_fc, b_fc, x, p_x1, ROWS, DD, DD);

    // 5) h = LN2(x1)
    ln_kernel<<<ROWS, 256>>>(p_x1, ln2_g, ln2_b, p_h);

    // 6) mid = gelu(h @ w1 + b1)              [4096 x 4096]
    gemm_mma<2><<<dim3(4*DD/128, ROWS/128), 256, GSMEM>>>(
        p_h, w1, b1, nullptr, p_mid, ROWS, 4*DD, DD);

    // 7) out = x1 + mid @ w2 + b2             [4096 x 1024]
    gemm_mma<1><<<dim3(DD/128, ROWS/128), 256, GSMEM>>>(
        p_mid, w2, b2, p_x1, out, ROWS, DD, 4*DD);
}

// round 6
// speedup vs baseline: 3.9925x; 1.2837x over previous
#include <cuda_runtime.h>
#include <cuda_bf16.h>
#include <math.h>
#include <stdint.h>

// Problem constants
#define BB 2
#define TT 2048
#define DD 1024
#define HH 16
#define HD 64
#define ROWS (BB*TT)          // 4096

// ---------------- scratch (device globals; no allocations) ----------------
__device__ float g_h   [ROWS * DD];
__device__ float g_qkv [ROWS * 3 * DD];
__device__ float g_att [ROWS * DD];
__device__ float g_x1  [ROWS * DD];
__device__ float g_mid [ROWS * 4 * DD];
// transposed weights
__device__ float g_wqkvT[3 * DD * DD];
__device__ float g_wfcT [DD * DD];
__device__ float g_w1T  [4 * DD * DD];
__device__ float g_w2T  [4 * DD * DD];

// ---------------- helpers -------------------------------------------------
__device__ __forceinline__ uint32_t smem_u32(const void* p) {
    uint32_t a;
    asm("{ .reg .u64 t; cvta.to.shared.u64 t, %1; cvt.u32.u64 %0, t; }"
        : "=r"(a) : "l"(p));
    return a;
}
__device__ __forceinline__ uint32_t f2tf(float f) {
    uint32_t u;
    asm("cvt.rna.tf32.f32 %0, %1;" : "=r"(u) : "f"(f));
    return u;
}
__device__ __forceinline__ void ldsm4(uint32_t& r0, uint32_t& r1,
                                      uint32_t& r2, uint32_t& r3, uint32_t a) {
    asm volatile("ldmatrix.sync.aligned.m8n8.x4.shared.b16 {%0,%1,%2,%3}, [%4];"
                 : "=r"(r0), "=r"(r1), "=r"(r2), "=r"(r3) : "r"(a));
}
__device__ __forceinline__ void mma8(float* c, const uint32_t* a, const uint32_t* b) {
    asm volatile(
        "mma.sync.aligned.m16n8k8.row.col.f32.tf32.tf32.f32 "
        "{%0,%1,%2,%3}, {%4,%5,%6,%7}, {%8,%9}, {%0,%1,%2,%3};"
        : "+f"(c[0]), "+f"(c[1]), "+f"(c[2]), "+f"(c[3])
        : "r"(a[0]), "r"(a[1]), "r"(a[2]), "r"(a[3]), "r"(b[0]), "r"(b[1]));
}
__device__ __forceinline__ void cp16(uint32_t dst, const void* src) {
    asm volatile("cp.async.cg.shared.global [%0], [%1], 16;"
                 :: "r"(dst), "l"(src));
}
__device__ __forceinline__ float gelu_exact(float v) {
    return 0.5f * v * (1.0f + erff(v * 0.70710678118654752f));
}

// ---------------- weight transpose: out[N,K] = in[K,N] --------------------
__global__ void transpose_kernel(const float* __restrict__ in,
                                 float* __restrict__ out, int K, int N) {
    __shared__ float t[32][33];
    int kx = blockIdx.x * 32, ny = blockIdx.y * 32;
    int x = threadIdx.x, y = threadIdx.y;  // 32 x 8
    #pragma unroll
    for (int i = 0; i < 32; i += 8)
        t[y + i][x] = in[(size_t)(kx + y + i) * N + ny + x];
    __syncthreads();
    #pragma unroll
    for (int i = 0; i < 32; i += 8)
        out[(size_t)(ny + y + i) * K + kx + x] = t[x][y + i];
}

// ---------------- LayerNorm ----------------------------------------------
__global__ void ln_kernel(const float* __restrict__ x,
                          const float* __restrict__ g,
                          const float* __restrict__ bvec,
                          float* __restrict__ out) {
    int row = blockIdx.x;
    int t   = threadIdx.x;
    const float4* xr = (const float4*)(x + (size_t)row * DD);
    float4 v = xr[t];
    float s  = v.x + v.y + v.z + v.w;
    float ss = v.x*v.x + v.y*v.y + v.z*v.z + v.w*v.w;
    #pragma unroll
    for (int o = 16; o > 0; o >>= 1) {
        s  += __shfl_xor_sync(0xffffffffu, s,  o);
        ss += __shfl_xor_sync(0xffffffffu, ss, o);
    }
    __shared__ float sh[2][8];
    int w = t >> 5, ln = t & 31;
    if (ln == 0) { sh[0][w] = s; sh[1][w] = ss; }
    __syncthreads();
    s = 0.f; ss = 0.f;
    #pragma unroll
    for (int i = 0; i < 8; i++) { s += sh[0][i]; ss += sh[1][i]; }
    float mu   = s * (1.0f / DD);
    float var  = ss * (1.0f / DD) - mu * mu;
    float rstd = rsqrtf(var + 1e-5f);
    float4 gg = ((const float4*)g)[t];
    float4 bb = ((const float4*)bvec)[t];
    float4 o4;
    o4.x = (v.x - mu) * rstd * gg.x + bb.x;
    o4.y = (v.y - mu) * rstd * gg.y + bb.y;
    o4.z = (v.z - mu) * rstd * gg.z + bb.z;
    o4.w = (v.w - mu) * rstd * gg.w + bb.w;
    ((float4*)(out + (size_t)row * DD))[t] = o4;
}

// ---------------- multistage cp.async tf32 GEMM ---------------------------
// C[M,N] = A[M,K] @ BT[N,K]^T  (+bias / +residual / GELU)
// Tile 128x128, BK=32, 3 stages, 256 threads, warp grid 2(M)x4(N).
// Both A and BT tiles: 128 rows x 32 floats, 128B rows, quad^(row&7) swizzle.
// fp32 fed raw to mma.tf32 (HW truncation).
#define GSTG 32768
#define GSMEM (3*GSTG)   // 98304

template <int EPI>
__global__ void __launch_bounds__(256)
gemm_ms(const float* __restrict__ A, const float* __restrict__ BT,
        const float* __restrict__ bias, const float* __restrict__ res,
        float* __restrict__ C, int M, int N, int K) {
    extern __shared__ char smem[];
    const uint32_t sb = smem_u32(smem);
    const int tid  = threadIdx.x;
    const int wid  = tid >> 5;
    const int lane = tid & 31;
    const int m0 = blockIdx.y * 128;
    const int n0 = blockIdx.x * 128;
    const int warp_m = (wid & 1) * 64;
    const int warp_n = (wid >> 1) * 32;

    const int rowA = (lane & 7) + ((lane >> 3) & 1) * 8;
    const int qselA = lane >> 4;
    const int lane7 = lane & 7;
    const int matB  = lane >> 3;

    float acc[4][4][4];
    #pragma unroll
    for (int i = 0; i < 4; i++)
        #pragma unroll
        for (int j = 0; j < 4; j++)
            #pragma unroll
            for (int q = 0; q < 4; q++) acc[i][j][q] = 0.f;

    const int nch = K / 32;

    // per-thread chunk coords for cp.async (4 A + 4 B chunks per stage)
    const float* Abase = A  + (size_t)m0 * K;
    const float* Bbase = BT + (size_t)n0 * K;

    auto load_stage = [&](int stg, int c) {
        const uint32_t ab = sb + stg * GSTG;
        const uint32_t bb = ab + 16384;
        const float* Ap = Abase + (size_t)c * 32;
        const float* Bp = Bbase + (size_t)c * 32;
        #pragma unroll
        for (int i = 0; i < 4; i++) {
            int idx = tid + i * 256;
            int r = idx >> 3, q = idx & 7;
            uint32_t off = (uint32_t)(r * 128 + ((q ^ (r & 7)) * 16));
            cp16(ab + off, Ap + (size_t)r * K + q * 4);
            cp16(bb + off, Bp + (size_t)r * K + q * 4);
        }
    };

    // prologue: stages 0,1
    load_stage(0, 0);
    asm volatile("cp.async.commit_group;" ::: "memory");
    if (nch > 1) load_stage(1, 1);
    asm volatile("cp.async.commit_group;" ::: "memory");

    for (int c = 0; c < nch; c++) {
        const int stg = c % 3;
        asm volatile("cp.async.wait_group 1;" ::: "memory");
        __syncthreads();

        // issue chunk c+2 into the buffer consumed at iter c-1
        if (c + 2 < nch) load_stage((c + 2) % 3, c + 2);
        asm volatile("cp.async.commit_group;" ::: "memory");

        const uint32_t As = sb + stg * GSTG;
        const uint32_t Bs = As + 16384;

        #pragma unroll
        for (int kb = 0; kb < 4; kb++) {
            uint32_t afr[4][4];
            uint32_t bfr[4][2];
            #pragma unroll
            for (int mb = 0; mb < 4; mb++) {
                int row = warp_m + mb * 16 + rowA;
                int quad = (2 * kb + qselA) ^ lane7;
                ldsm4(afr[mb][0], afr[mb][1], afr[mb][2], afr[mb][3],
                      As + (uint32_t)(row * 128 + quad * 16));
            }
            #pragma unroll
            for (int s = 0; s < 2; s++) {
                int nb = 2 * s + (matB >> 1);
                int n = warp_n + nb * 8 + lane7;
                int quad = (2 * kb + (matB & 1)) ^ lane7;
                ldsm4(bfr[2*s][0], bfr[2*s][1], bfr[2*s+1][0], bfr[2*s+1][1],
                      Bs + (uint32_t)(n * 128 + quad * 16));
            }
            #pragma unroll
            for (int mb = 0; mb < 4; mb++)
                #pragma unroll
                for (int nb = 0; nb < 4; nb++)
                    mma8(acc[mb][nb], afr[mb], bfr[nb]);
        }
        __syncthreads();
    }

    // ---- epilogue ----
    const int gr = lane >> 2;
    const int cp = (lane & 3) * 2;
    #pragma unroll
    for (int mb = 0; mb < 4; mb++) {
        #pragma unroll
        for (int nb = 0; nb < 4; nb++) {
            int row0 = m0 + warp_m + mb * 16 + gr;
            int col  = n0 + warp_n + nb * 8 + cp;
            float2 bi = *(const float2*)&bias[col];
            float v0 = acc[mb][nb][0] + bi.x;
            float v1 = acc[mb][nb][1] + bi.y;
            float v2 = acc[mb][nb][2] + bi.x;
            float v3 = acc[mb][nb][3] + bi.y;
            if (EPI == 1) {
                float2 r0 = *(const float2*)&res[(size_t)row0 * N + col];
                float2 r1 = *(const float2*)&res[(size_t)(row0 + 8) * N + col];
                v0 += r0.x; v1 += r0.y; v2 += r1.x; v3 += r1.y;
            }
            if (EPI == 2) {
                v0 = gelu_exact(v0); v1 = gelu_exact(v1);
                v2 = gelu_exact(v2); v3 = gelu_exact(v3);
            }
            *(float2*)&C[(size_t)row0 * N + col]       = make_float2(v0, v1);
            *(float2*)&C[(size_t)(row0 + 8) * N + col] = make_float2(v2, v3);
        }
    }
}

// ---------------- tensor-core flash attention (unchanged from R5) ---------
#define AQLO 0
#define AQHI 16384
#define AKLO 32768
#define AKHI 49152
#define AVT  65536
#define APS  98304
#define ASMM 163840
#define ASMS 164864
#define ATT_SMEM 165888

__global__ void __launch_bounds__(256)
attn_mma() {
    extern __shared__ char smem[];
    const uint32_t sb = smem_u32(smem);
    float* smf = (float*)smem;

    const int qblk = gridDim.x - 1 - blockIdx.x;
    const int bh = blockIdx.y;
    const int b = bh >> 4, h = bh & 15;
    const int q0 = qblk * 128;

    const float* base = g_qkv + (size_t)b * TT * 3 * DD;
    const float* qb = base + h * HD;
    const float* kb_ = base + DD + h * HD;
    const float* vb = base + 2 * DD + h * HD;

    const int tid = threadIdx.x, wid = tid >> 5, lane = tid & 31;
    const int gr = lane >> 2, qd = lane & 3;
    const int warp_m  = (wid & 3) * 32;
    const int warp_ns = (wid >> 2) * 64;
    const int warp_np = (wid >> 2) * 32;
    const int slot = wid >> 2;

    const int rowA = (lane & 7) + ((lane >> 3) & 1) * 8;
    const int qselA = lane >> 4;
    const int lane7 = lane & 7, matB = lane >> 3;

    #pragma unroll
    for (int i = 0; i < 8; i++) {
        int idx = tid + i * 256;
        int r = idx >> 4, c4 = idx & 15;
        float4 v = *(const float4*)(qb + (size_t)(q0 + r) * 3 * DD + c4 * 4);
        uint32_t off = (c4 < 8 ? AQLO : AQHI) +
                       (uint32_t)(r * 128 + (((c4 & 7) ^ (r & 7)) * 16));
        uint4 u = make_uint4(f2tf(v.x * 0.125f), f2tf(v.y * 0.125f),
                             f2tf(v.z * 0.125f), f2tf(v.w * 0.125f));
        *(uint4*)(smem + off) = u;
    }

    float m_old[4], lsum[4];
    #pragma unroll
    for (int i = 0; i < 4; i++) { m_old[i] = -1e30f; lsum[i] = 0.f; }
    float o[2][4][4];
    #pragma unroll
    for (int mb = 0; mb < 2; mb++)
        #pragma unroll
        for (int nb = 0; nb < 4; nb++)
            #pragma unroll
            for (int q = 0; q < 4; q++) o[mb][nb][q] = 0.f;

    int rloc[4];
    #pragma unroll
    for (int i = 0; i < 4; i++)
        rloc[i] = warp_m + (i >> 1) * 16 + (i & 1) * 8 + gr;

    for (int kt = 0; kt <= qblk; kt++) {
        __syncthreads();

        #pragma unroll
        for (int i = 0; i < 8; i++) {
            int idx = tid + i * 256;
            int r = idx >> 4, c4 = idx & 15;
            float4 v = *(const float4*)(kb_ + (size_t)(kt * 128 + r) * 3 * DD + c4 * 4);
            uint32_t off = (c4 < 8 ? AKLO : AKHI) +
                           (uint32_t)(r * 128 + (((c4 & 7) ^ (r & 7)) * 16));
            *(uint4*)(smem + off) = make_uint4(f2tf(v.x), f2tf(v.y), f2tf(v.z), f2tf(v.w));
        }
        #pragma unroll
        for (int i = 0; i < 2; i++) {
            int lin = tid + i * 256;
            int kq = lin & 31, hq = lin >> 5;
            const float* vp = vb + (size_t)(kt * 128 + kq * 4) * 3 * DD + hq * 4;
            float4 r0 = *(const float4*)(vp);
            float4 r1 = *(const float4*)(vp + 3 * DD);
            float4 r2 = *(const float4*)(vp + 6 * DD);
            float4 r3 = *(const float4*)(vp + 9 * DD);
            float wsx[4] = {r0.x, r1.x, r2.x, r3.x};
            float wsy[4] = {r0.y, r1.y, r2.y, r3.y};
            float wsz[4] = {r0.z, r1.z, r2.z, r3.z};
            float wsw[4] = {r0.w, r1.w, r2.w, r3.w};
            #pragma unroll
            for (int s = 0; s < 4; s++) {
                int t = (s + kq) & 3;
                int hd = hq * 4 + t;
                float* col = (t == 0) ? wsx : (t == 1) ? wsy : (t == 2) ? wsz : wsw;
                uint32_t off = AVT + (kq >> 3) * 8192 +
                               (uint32_t)(hd * 128 + (((kq & 7) ^ (hd & 7)) * 16));
                *(uint4*)(smem + off) =
                    make_uint4(f2tf(col[0]), f2tf(col[1]), f2tf(col[2]), f2tf(col[3]));
            }
        }
        __syncthreads();

        float sacc[2][8][4];
        #pragma unroll
        for (int mb = 0; mb < 2; mb++)
            #pragma unroll
            for (int nb = 0; nb < 8; nb++)
                #pragma unroll
                for (int q = 0; q < 4; q++) sacc[mb][nb][q] = 0.f;

        #pragma unroll
        for (int kb = 0; kb < 8; kb++) {
            const uint32_t Ab = sb + (kb < 4 ? AQLO : AQHI);
            const uint32_t Bb = sb + (kb < 4 ? AKLO : AKHI);
            const int ks = kb & 3;
            uint32_t afr[2][4], bfr[8][2];
            #pragma unroll
            for (int mb = 0; mb < 2; mb++) {
                int row = warp_m + mb * 16 + rowA;
                int quad = (2 * ks + qselA) ^ (rowA & 7);
                ldsm4(afr[mb][0], afr[mb][1], afr[mb][2], afr[mb][3],
                      Ab + (uint32_t)(row * 128 + quad * 16));
            }
            #pragma unroll
            for (int s = 0; s < 4; s++) {
                int nb = 2 * s + (matB >> 1);
                int n = warp_ns + nb * 8 + lane7;
                int quad = (2 * ks + (matB & 1)) ^ lane7;
                ldsm4(bfr[2*s][0], bfr[2*s][1], bfr[2*s+1][0], bfr[2*s+1][1],
                      Bb + (uint32_t)(n * 128 + quad * 16));
            }
            #pragma unroll
            for (int mb = 0; mb < 2; mb++)
                #pragma unroll
                for (int nb = 0; nb < 8; nb++)
                    mma8(sacc[mb][nb], afr[mb], bfr[nb]);
        }

        if (kt == qblk) {
            #pragma unroll
            for (int mb = 0; mb < 2; mb++)
                #pragma unroll
                for (int half = 0; half < 2; half++) {
                    int rowg = q0 + rloc[mb * 2 + half];
                    #pragma unroll
                    for (int nb = 0; nb < 8; nb++)
                        #pragma unroll
                        for (int j = 0; j < 2; j++) {
                            int col = kt * 128 + warp_ns + nb * 8 + 2 * qd + j;
                            if (col > rowg) sacc[mb][nb][half * 2 + j] = -1e30f;
                        }
                }
        }

        float mt[4];
        #pragma unroll
        for (int i = 0; i < 4; i++) {
            int mb = i >> 1, half = i & 1;
            float v = -1e30f;
            #pragma unroll
            for (int nb = 0; nb < 8; nb++) {
                v = fmaxf(v, sacc[mb][nb][half * 2 + 0]);
                v = fmaxf(v, sacc[mb][nb][half * 2 + 1]);
            }
            v = fmaxf(v, __shfl_xor_sync(0xffffffffu, v, 1));
            v = fmaxf(v, __shfl_xor_sync(0xffffffffu, v, 2));
            mt[i] = v;
        }
        if (qd == 0) {
            #pragma unroll
            for (int i = 0; i < 4; i++)
                smf[(ASMM >> 2) + slot * 128 + rloc[i]] = mt[i];
        }
        __syncthreads();

        float mnew[4], sc[4];
        #pragma unroll
        for (int i = 0; i < 4; i++) {
            float mfull = fmaxf(smf[(ASMM >> 2) + rloc[i]],
                                smf[(ASMM >> 2) + 128 + rloc[i]]);
            mnew[i] = fmaxf(m_old[i], mfull);
            sc[i] = __expf(m_old[i] - mnew[i]);
            m_old[i] = mnew[i];
        }

        float ts[4] = {0.f, 0.f, 0.f, 0.f};
        #pragma unroll
        for (int mb = 0; mb < 2; mb++)
            #pragma unroll
            for (int half = 0; half < 2; half++) {
                int i = mb * 2 + half;
                #pragma unroll
                for (int nb = 0; nb < 8; nb++) {
                    float p0 = __expf(sacc[mb][nb][half * 2 + 0] - mnew[i]);
                    float p1 = __expf(sacc[mb][nb][half * 2 + 1] - mnew[i]);
                    sacc[mb][nb][half * 2 + 0] = p0;
                    sacc[mb][nb][half * 2 + 1] = p1;
                    ts[i] += p0 + p1;
                }
            }
        #pragma unroll
        for (int i = 0; i < 4; i++) {
            ts[i] += __shfl_xor_sync(0xffffffffu, ts[i], 1);
            ts[i] += __shfl_xor_sync(0xffffffffu, ts[i], 2);
        }
        if (qd == 0) {
            #pragma unroll
            for (int i = 0; i < 4; i++)
                smf[(ASMS >> 2) + slot * 128 + rloc[i]] = ts[i];
        }
        #pragma unroll
        for (int mb = 0; mb < 2; mb++)
            #pragma unroll
            for (int nb = 0; nb < 4; nb++) {
                o[mb][nb][0] *= sc[mb * 2 + 0];
                o[mb][nb][1] *= sc[mb * 2 + 0];
                o[mb][nb][2] *= sc[mb * 2 + 1];
                o[mb][nb][3] *= sc[mb * 2 + 1];
            }
        #pragma unroll
        for (int i = 0; i < 4; i++) lsum[i] *= sc[i];
        __syncthreads();
        #pragma unroll
        for (int i = 0; i < 4; i++)
            lsum[i] += smf[(ASMS >> 2) + rloc[i]] + smf[(ASMS >> 2) + 128 + rloc[i]];

        #pragma unroll
        for (int mb = 0; mb < 2; mb++)
            #pragma unroll
            for (int half = 0; half < 2; half++) {
                int row = rloc[mb * 2 + half];
                #pragma unroll
                for (int nb = 0; nb < 8; nb++) {
                    int col0 = warp_ns + nb * 8 + 2 * qd;
                    int cbuf = col0 >> 5, c5 = col0 & 31;
                    uint32_t addr = APS + cbuf * 16384 +
                        (uint32_t)(row * 128 + (((c5 >> 2) ^ (row & 7)) * 16) + (c5 & 3) * 4);
                    uint2 u = make_uint2(f2tf(sacc[mb][nb][half * 2 + 0]),
                                         f2tf(sacc[mb][nb][half * 2 + 1]));
                    *(uint2*)(smem + addr) = u;
                }
            }
        __syncthreads();

        #pragma unroll
        for (int ksx = 0; ksx < 16; ksx++) {
            const uint32_t Pb = sb + APS + (ksx >> 2) * 16384;
            const uint32_t Vb = sb + AVT + (ksx >> 2) * 8192;
            const int kk = ksx & 3;
            uint32_t afr[2][4], bfr[4][2];
            #pragma unroll
            for (int mb = 0; mb < 2; mb++) {
                int row = warp_m + mb * 16 + rowA;
                int quad = (2 * kk + qselA) ^ (rowA & 7);
                ldsm4(afr[mb][0], afr[mb][1], afr[mb][2], afr[mb][3],
                      Pb + (uint32_t)(row * 128 + quad * 16));
            }
            #pragma unroll
            for (int s = 0; s < 2; s++) {
                int nb = 2 * s + (matB >> 1);
                int n = warp_np + nb * 8 + lane7;
                int quad = (2 * kk + (matB & 1)) ^ lane7;
                ldsm4(bfr[2*s][0], bfr[2*s][1], bfr[2*s+1][0], bfr[2*s+1][1],
                      Vb + (uint32_t)(n * 128 + quad * 16));
            }
            #pragma unroll
            for (int mb = 0; mb < 2; mb++)
                #pragma unroll
                for (int nb = 0; nb < 4; nb++)
                    mma8(o[mb][nb], afr[mb], bfr[nb]);
        }
    }

    float inv[4];
    #pragma unroll
    for (int i = 0; i < 4; i++) inv[i] = 1.0f / lsum[i];
    #pragma unroll
    for (int mb = 0; mb < 2; mb++)
        #pragma unroll
        for (int half = 0; half < 2; half++) {
            int i = mb * 2 + half;
            int row = q0 + rloc[i];
            #pragma unroll
            for (int nb = 0; nb < 4; nb++) {
                int col = warp_np + nb * 8 + 2 * qd;
                float2 w = make_float2(o[mb][nb][half * 2 + 0] * inv[i],
                                       o[mb][nb][half * 2 + 1] * inv[i]);
                *(float2*)&g_att[((size_t)b * TT + row) * DD + h * HD + col] = w;
            }
        }
}

// ---------------- launch -------------------------------------------------
extern "C" void kernel_launch(void* const* d_in, const int* in_sizes, int n_in,
                              void* d_out, int out_size) {
    const float* x     = (const float*)d_in[0];
    const float* w_qkv = (const float*)d_in[1];
    const float* b_qkv = (const float*)d_in[2];
    const float* w_fc  = (const float*)d_in[3];
    const float* b_fc  = (const float*)d_in[4];
    const float* ln1_g = (const float*)d_in[5];
    const float* ln1_b = (const float*)d_in[6];
    const float* ln2_g = (const float*)d_in[7];
    const float* ln2_b = (const float*)d_in[8];
    const float* w1    = (const float*)d_in[9];
    const float* b1    = (const float*)d_in[10];
    const float* w2    = (const float*)d_in[11];
    const float* b2    = (const float*)d_in[12];
    float* out = (float*)d_out;

    float *p_h, *p_qkv, *p_att, *p_x1, *p_mid;
    float *p_wqkvT, *p_wfcT, *p_w1T, *p_w2T;
    cudaGetSymbolAddress((void**)&p_h,    g_h);
    cudaGetSymbolAddress((void**)&p_qkv,  g_qkv);
    cudaGetSymbolAddress((void**)&p_att,  g_att);
    cudaGetSymbolAddress((void**)&p_x1,   g_x1);
    cudaGetSymbolAddress((void**)&p_mid,  g_mid);
    cudaGetSymbolAddress((void**)&p_wqkvT, g_wqkvT);
    cudaGetSymbolAddress((void**)&p_wfcT,  g_wfcT);
    cudaGetSymbolAddress((void**)&p_w1T,   g_w1T);
    cudaGetSymbolAddress((void**)&p_w2T,   g_w2T);

    cudaFuncSetAttribute(gemm_ms<0>, cudaFuncAttributeMaxDynamicSharedMemorySize, GSMEM);
    cudaFuncSetAttribute(gemm_ms<1>, cudaFuncAttributeMaxDynamicSharedMemorySize, GSMEM);
    cudaFuncSetAttribute(gemm_ms<2>, cudaFuncAttributeMaxDynamicSharedMemorySize, GSMEM);
    cudaFuncSetAttribute(attn_mma,   cudaFuncAttributeMaxDynamicSharedMemorySize, ATT_SMEM);

    dim3 tb(32, 8);
    // 0) transpose weights
    transpose_kernel<<<dim3(DD/32, 3*DD/32), tb>>>(w_qkv, p_wqkvT, DD, 3*DD);
    transpose_kernel<<<dim3(DD/32, DD/32),   tb>>>(w_fc,  p_wfcT,  DD, DD);
    transpose_kernel<<<dim3(DD/32, 4*DD/32), tb>>>(w1,    p_w1T,   DD, 4*DD);
    transpose_kernel<<<dim3(4*DD/32, DD/32), tb>>>(w2,    p_w2T,   4*DD, DD);

    // 1) h = LN1(x)
    ln_kernel<<<ROWS, 256>>>(x, ln1_g, ln1_b, p_h);

    // 2) qkv = h @ w_qkv + b_qkv              [4096 x 3072]
    gemm_ms<0><<<dim3(3*DD/128, ROWS/128), 256, GSMEM>>>(
        p_h, p_wqkvT, b_qkv, nullptr, p_qkv, ROWS, 3*DD, DD);

    // 3) causal attention -> g_att            [4096 x 1024]
    attn_mma<<<dim3(TT/128, BB*HH), 256, ATT_SMEM>>>();

    // 4) x1 = x + att @ w_fc + b_fc           [4096 x 1024]
    gemm_ms<1><<<dim3(DD/128, ROWS/128), 256, GSMEM>>>(
        p_att, p_wfcT, b_fc, x, p_x1, ROWS, DD, DD);

    // 5) h = LN2(x1)
    ln_kernel<<<ROWS, 256>>>(p_x1, ln2_g, ln2_b, p_h);

    // 6) mid = gelu(h @ w1 + b1)              [4096 x 4096]
    gemm_ms<2><<<dim3(4*DD/128, ROWS/128), 256, GSMEM>>>(
        p_h, p_w1T, b1, nullptr, p_mid, ROWS, 4*DD, DD);

    // 7) out = x1 + mid @ w2 + b2             [4096 x 1024]
    gemm_ms<1><<<dim3(DD/128, ROWS/128), 256, GSMEM>>>(
        p_mid, p_w2T, b2, p_x1, out, ROWS, DD, 4*DD);
}